// round 12
// baseline (speedup 1.0000x reference)
#include <cuda_runtime.h>
#include <cuda_fp16.h>
#include <cstdint>
#include <math.h>

// Problem constants
#define BB 4
#define SS 2048
#define DD 1024
#define HH 16
#define DH 64

// ---------------------------------------------------------------------------
// Scratch (device globals — no runtime allocation allowed)
// ---------------------------------------------------------------------------
__device__ __half g_qkvh [(long)BB * SS * 3 * DD];  // QKV (fp16)
__device__ __half g_hoph [(long)BB * SS * SS];      // hopping bias (fp16)
__device__ __half g_attnh[(long)BB * SS * DD];      // attention out (fp16)
__device__ float  g_att2 [(long)BB * SS * DD];      // after O-proj (fp32)
__device__ float  g_x1   [(long)BB * SS * DD];      // after LN1 (fp32, exact)
__device__ __half g_x1h  [(long)BB * SS * DD];      // after LN1 (fp16)
__device__ __half g_f1h  [(long)BB * SS * 4 * DD];  // after FFN1+GELU (fp16)
__device__ float  g_ff2  [(long)BB * SS * DD];      // after FFN2 (fp32)
// fp16 copies of inputs
__device__ __half g_xh   [(long)BB * SS * DD];
__device__ __half g_imh  [(long)BB * SS * DD];
__device__ __half g_wqkvh[(long)3 * DD * DD];
__device__ __half g_woh  [(long)DD * DD];
__device__ __half g_w1h  [(long)4 * DD * DD];
__device__ __half g_w2h  [(long)DD * 4 * DD];

// ---------------------------------------------------------------------------
// Helpers
// ---------------------------------------------------------------------------
__device__ __forceinline__ float gelu_exact(float x) {
    return 0.5f * x * (1.0f + erff(x * 0.70710678118654752f));
}
__device__ __forceinline__ unsigned packh2(float a, float b) {
    __half2 h = __floats2half2_rn(a, b);
    return *(unsigned*)&h;
}
// ex2 on packed fp16x2: one MUFU op for two exponentials (2^x)
__device__ __forceinline__ unsigned h2ex2(unsigned x) {
    unsigned r;
    asm("ex2.approx.f16x2 %0, %1;" : "=r"(r) : "r"(x));
    return r;
}
__device__ __forceinline__ void cp_async16(unsigned saddr, const void* gmem) {
    asm volatile("cp.async.cg.shared.global [%0], [%1], 16;" :: "r"(saddr), "l"(gmem));
}
__device__ __forceinline__ void cp_commit() { asm volatile("cp.async.commit_group;"); }
template<int N> __device__ __forceinline__ void cp_wait() {
    asm volatile("cp.async.wait_group %0;" :: "n"(N));
}

// m16n8k16 fp16 mma, fp32 accumulate
__device__ __forceinline__ void mma_f16(float* c, const unsigned* a,
                                        unsigned b0, unsigned b1) {
    asm volatile(
        "mma.sync.aligned.m16n8k16.row.col.f32.f16.f16.f32 "
        "{%0,%1,%2,%3}, {%4,%5,%6,%7}, {%8,%9}, {%0,%1,%2,%3};"
        : "+f"(c[0]), "+f"(c[1]), "+f"(c[2]), "+f"(c[3])
        : "r"(a[0]), "r"(a[1]), "r"(a[2]), "r"(a[3]), "r"(b0), "r"(b1));
}

#define LDSM4(r0, r1, r2, r3, saddr) \
    asm volatile("ldmatrix.sync.aligned.m8n8.x4.shared.b16 {%0,%1,%2,%3}, [%4];" \
                 : "=r"(r0), "=r"(r1), "=r"(r2), "=r"(r3) : "r"(saddr))
#define LDSM4T(r0, r1, r2, r3, saddr) \
    asm volatile("ldmatrix.sync.aligned.m8n8.x4.trans.shared.b16 {%0,%1,%2,%3}, [%4];" \
                 : "=r"(r0), "=r"(r1), "=r"(r2), "=r"(r3) : "r"(saddr))

// Epilogue store helpers (fp32 or fp16 output)
__device__ __forceinline__ void store2(float* C, long idx, float a, float b) {
    *(float2*)&C[idx] = make_float2(a, b);
}
__device__ __forceinline__ void store2(__half* C, long idx, float a, float b) {
    *(unsigned*)&C[idx] = packh2(a, b);
}

// ---------------------------------------------------------------------------
// Elementwise fp32 -> fp16 convert (8 per thread)
// ---------------------------------------------------------------------------
__global__ __launch_bounds__(256)
void cvt_kernel(const float* __restrict__ in, __half* __restrict__ out, long n)
{
    long i = ((long)blockIdx.x * 256 + threadIdx.x) * 8;
    if (i >= n) return;
    float4 v0 = *(const float4*)&in[i];
    float4 v1 = *(const float4*)&in[i + 4];
    uint4 q;
    q.x = packh2(v0.x, v0.y);
    q.y = packh2(v0.z, v0.w);
    q.z = packh2(v1.x, v1.y);
    q.w = packh2(v1.z, v1.w);
    *(uint4*)&out[i] = q;
}

// ---------------------------------------------------------------------------
// FP16 tensor-core GEMM, ldmatrix fragments, 4-stage cp.async pipeline.
// C[M,N] = scale * (A[M,K] @ B[N,K]^T) + bias[N], optional exact GELU.
// 128x256x32 CTA tile, 256 threads, 8 warps (2x4), warp tile 64x64.
// Requires M%128==0, N%256==0, K%32==0, K/32>=3. causal => skip upper tiles.
// ---------------------------------------------------------------------------
#define SPADH 40                          // halves per smem row (80 B)
#define ASTG (128 * SPADH * 2)            // 10240 B
#define BSTG (256 * SPADH * 2)            // 20480 B
#define STGB (ASTG + BSTG)                // 30720 B per stage
#define GEMM_SMEM (4 * STGB)              // 122880 B

template<bool GELU, typename OutT>
__global__ __launch_bounds__(256, 1)
void hgemm(const __half* __restrict__ A, const __half* __restrict__ B,
           const float* __restrict__ bias, OutT* __restrict__ C,
           int M, int N, int K, long sA, long sB, long sC,
           float scale, int causal)
{
    extern __shared__ __half smem[];
    const unsigned sb = (unsigned)__cvta_generic_to_shared(smem);

    const int tid  = threadIdx.x;
    const int warp = tid >> 5;
    const int lane = tid & 31;
    const int g    = lane >> 2;
    const int t    = lane & 3;
    const int m0   = blockIdx.y * 128;
    const int n0   = blockIdx.x * 256;

    if (causal && n0 > m0 + 127) return;

    const int z = blockIdx.z;
    A += (long)z * sA;
    B += (long)z * sB;
    C += (long)z * sC;

    const int wm = (warp & 1) * 64;    // warp m offset (0,64)
    const int wn = (warp >> 1) * 64;   // warp n offset (0,64,128,192)

    float acc[4][8][4];
    #pragma unroll
    for (int mi = 0; mi < 4; mi++)
        #pragma unroll
        for (int ni = 0; ni < 8; ni++)
            #pragma unroll
            for (int c = 0; c < 4; c++)
                acc[mi][ni][c] = 0.0f;

    const int raA = wm + (lane & 7) + (((lane >> 3) & 1) << 3);
    const int caA = ((lane >> 4) << 3);
    const int raB = wn + (lane & 7) + ((lane >> 4) << 3);
    const int caB = (((lane >> 3) & 1) << 3);

    const int niter = K >> 5;

    #define STAGE(s, k0)                                                        \
        {                                                                       \
            unsigned ab = sb + (s) * STGB;                                      \
            unsigned bb = ab + ASTG;                                            \
            _Pragma("unroll")                                                   \
            for (int l = 0; l < 2; l++) {                                       \
                int idx = l * 256 + tid;                                        \
                int row = idx >> 2, cc = idx & 3;                               \
                cp_async16(ab + (row * SPADH + cc * 8) * 2,                     \
                           &A[(long)(m0 + row) * K + (k0) + cc * 8]);           \
            }                                                                   \
            _Pragma("unroll")                                                   \
            for (int l = 0; l < 4; l++) {                                       \
                int idx = l * 256 + tid;                                        \
                int row = idx >> 2, cc = idx & 3;                               \
                cp_async16(bb + (row * SPADH + cc * 8) * 2,                     \
                           &B[(long)(n0 + row) * K + (k0) + cc * 8]);           \
            }                                                                   \
        }

    STAGE(0, 0);  cp_commit();
    STAGE(1, 32); cp_commit();
    STAGE(2, 64); cp_commit();

    for (int i = 0; i < niter; i++) {
        cp_wait<2>();
        __syncthreads();

        const unsigned As = sb + (i & 3) * STGB;
        const unsigned Bs = As + ASTG;

        #pragma unroll
        for (int ks = 0; ks < 2; ks++) {
            const int kb = ks * 16;
            unsigned a[4][4], b[4][4];
            #pragma unroll
            for (int mi = 0; mi < 4; mi++)
                LDSM4(a[mi][0], a[mi][1], a[mi][2], a[mi][3],
                      As + ((raA + mi * 16) * SPADH + kb + caA) * 2);
            #pragma unroll
            for (int nj = 0; nj < 4; nj++)
                LDSM4(b[nj][0], b[nj][1], b[nj][2], b[nj][3],
                      Bs + ((raB + nj * 16) * SPADH + kb + caB) * 2);
            #pragma unroll
            for (int mi = 0; mi < 4; mi++)
                #pragma unroll
                for (int nj = 0; nj < 4; nj++) {
                    mma_f16(acc[mi][2 * nj    ], a[mi], b[nj][0], b[nj][1]);
                    mma_f16(acc[mi][2 * nj + 1], a[mi], b[nj][2], b[nj][3]);
                }
        }

        if (i + 3 < niter) STAGE((i + 3) & 3, (i + 3) * 32);
        cp_commit();
    }
    #undef STAGE

    // Epilogue
    #pragma unroll
    for (int mi = 0; mi < 4; mi++) {
        const int row0 = m0 + wm + mi * 16 + g;
        #pragma unroll
        for (int ni = 0; ni < 8; ni++) {
            const int col = n0 + wn + ni * 8 + 2 * t;
            float bx = 0.0f, by = 0.0f;
            if (bias) { bx = bias[col]; by = bias[col + 1]; }
            float o0 = acc[mi][ni][0] * scale + bx;
            float o1 = acc[mi][ni][1] * scale + by;
            float o2 = acc[mi][ni][2] * scale + bx;
            float o3 = acc[mi][ni][3] * scale + by;
            if (GELU) {
                o0 = gelu_exact(o0); o1 = gelu_exact(o1);
                o2 = gelu_exact(o2); o3 = gelu_exact(o3);
            }
            store2(C, (long)row0 * N + col, o0, o1);
            store2(C, (long)(row0 + 8) * N + col, o2, o3);
        }
    }
}

// ---------------------------------------------------------------------------
// FP16 tensor-core flash attention, 128-row q tile, fp16 hopping bias.
// Softmax exponentials via ex2.approx.f16x2 (2 per MUFU op); the half2
// results are used directly as PV A-fragments.
// Grid: (S/128, H, B). Block: 256 threads (8 warps).
// ---------------------------------------------------------------------------
#define KPAD 72
#define LOG2E 1.4426950408889634f
__global__ __launch_bounds__(256, 2)
void attn_kernel(const __half* __restrict__ qkv, const __half* __restrict__ hop,
                 __half* __restrict__ out)
{
    __shared__ __half Ks[64][KPAD];   // [key][d]
    __shared__ __half Vs[64][KPAD];   // [key][d]

    const int tid  = threadIdx.x;
    const int lane = tid & 31;
    const int warp = tid >> 5;
    const int g    = lane >> 2;
    const int t    = lane & 3;
    const int qb = blockIdx.x, h = blockIdx.y, b = blockIdx.z;
    const int q0 = qb * 128;
    const long rowbase = (long)b * SS * (3 * DD);
    const long hb      = (long)b * SS * SS;
    const int rg0 = q0 + warp * 16 + g;   // first owned row (global)
    const int rg1 = rg0 + 8;

    const unsigned ksb = (unsigned)__cvta_generic_to_shared(&Ks[0][0]);
    const unsigned vsb = (unsigned)__cvta_generic_to_shared(&Vs[0][0]);
    const int rB = (lane & 7) + ((lane >> 4) << 3);          // non-trans rows
    const int cB = (((lane >> 3) & 1) << 3);                 // non-trans col half
    const int rT = (lane & 7) + (((lane >> 3) & 1) << 3);    // trans rows (keys)
    const int cT = ((lane >> 4) << 3);                       // trans col half (d)

    // ---- Q A-fragments straight from gmem ----
    unsigned qa[4][4];
    {
        const long q0r = rowbase + (long)rg0 * (3 * DD) + h * DH;
        const long q1r = rowbase + (long)rg1 * (3 * DD) + h * DH;
        #pragma unroll
        for (int ks = 0; ks < 4; ks++) {
            const int kb = ks * 16 + 2 * t;
            qa[ks][0] = *(const unsigned*)&qkv[q0r + kb];
            qa[ks][1] = *(const unsigned*)&qkv[q1r + kb];
            qa[ks][2] = *(const unsigned*)&qkv[q0r + kb + 8];
            qa[ks][3] = *(const unsigned*)&qkv[q1r + kb + 8];
        }
    }

    float mr0 = -1e30f, mr1 = -1e30f, ls0 = 0.0f, ls1 = 0.0f;
    float oacc[8][4];
    #pragma unroll
    for (int ni = 0; ni < 8; ni++)
        #pragma unroll
        for (int c = 0; c < 4; c++) oacc[ni][c] = 0.0f;

    const int ktmax = 2 * qb + 2;
    for (int kt = 0; kt < ktmax; kt++) {
        const int k0 = kt * 64;

        // Stage K and V (row-major, vectorized, conflict-free)
        #pragma unroll
        for (int l = 0; l < 2; l++) {
            int idx = tid + l * 256, r = idx >> 3, c = (idx & 7) * 8;
            long base = rowbase + (long)(k0 + r) * (3 * DD) + h * DH + c;
            *(uint4*)&Ks[r][c] = *(const uint4*)&qkv[base + DD];
            *(uint4*)&Vs[r][c] = *(const uint4*)&qkv[base + 2 * DD];
        }
        __syncthreads();

        // Hopping bias prefetch (fp16 -> fp32)
        float2 hp0[8], hp1[8];
        #pragma unroll
        for (int ni = 0; ni < 8; ni++) {
            __half2 u0 = *(const __half2*)&hop[hb + (long)rg0 * SS + k0 + ni * 8 + 2 * t];
            __half2 u1 = *(const __half2*)&hop[hb + (long)rg1 * SS + k0 + ni * 8 + 2 * t];
            hp0[ni] = __half22float2(u0);
            hp1[ni] = __half22float2(u1);
        }

        // S = Q @ K^T
        float sacc[8][4];
        #pragma unroll
        for (int ni = 0; ni < 8; ni++)
            #pragma unroll
            for (int c = 0; c < 4; c++) sacc[ni][c] = 0.0f;
        #pragma unroll
        for (int ks = 0; ks < 4; ks++) {
            const int kb = ks * 16;
            #pragma unroll
            for (int nj = 0; nj < 4; nj++) {
                unsigned b0, b1, b2, b3;
                LDSM4(b0, b1, b2, b3,
                      ksb + ((nj * 16 + rB) * KPAD + kb + cB) * 2);
                mma_f16(sacc[2 * nj    ], qa[ks], b0, b1);
                mma_f16(sacc[2 * nj + 1], qa[ks], b2, b3);
            }
        }

        // scale + bias (+ causal mask on diagonal-straddling tiles)
        #pragma unroll
        for (int ni = 0; ni < 8; ni++) {
            sacc[ni][0] = sacc[ni][0] * 0.125f + hp0[ni].x;
            sacc[ni][1] = sacc[ni][1] * 0.125f + hp0[ni].y;
            sacc[ni][2] = sacc[ni][2] * 0.125f + hp1[ni].x;
            sacc[ni][3] = sacc[ni][3] * 0.125f + hp1[ni].y;
        }
        if (kt >= 2 * qb) {   // global row/col compare
            #pragma unroll
            for (int ni = 0; ni < 8; ni++) {
                int c0 = k0 + ni * 8 + 2 * t, c1 = c0 + 1;
                if (c0 > rg0) sacc[ni][0] = -1e30f;
                if (c1 > rg0) sacc[ni][1] = -1e30f;
                if (c0 > rg1) sacc[ni][2] = -1e30f;
                if (c1 > rg1) sacc[ni][3] = -1e30f;
            }
        }

        // Warp-local online softmax (max in fp32)
        float rm0 = -1e30f, rm1 = -1e30f;
        #pragma unroll
        for (int ni = 0; ni < 8; ni++) {
            rm0 = fmaxf(rm0, fmaxf(sacc[ni][0], sacc[ni][1]));
            rm1 = fmaxf(rm1, fmaxf(sacc[ni][2], sacc[ni][3]));
        }
        rm0 = fmaxf(rm0, __shfl_xor_sync(0xffffffffu, rm0, 1));
        rm0 = fmaxf(rm0, __shfl_xor_sync(0xffffffffu, rm0, 2));
        rm1 = fmaxf(rm1, __shfl_xor_sync(0xffffffffu, rm1, 1));
        rm1 = fmaxf(rm1, __shfl_xor_sync(0xffffffffu, rm1, 2));

        const float nm0 = fmaxf(mr0, rm0), nm1 = fmaxf(mr1, rm1);
        const float sc0 = __expf(mr0 - nm0), sc1 = __expf(mr1 - nm1);

        // P = 2^((s-m)*log2e) via packed fp16x2 ex2; the half2 results are
        // directly the PV A-fragment registers. Row-sums in fp32.
        unsigned ph[8][2];
        float rs0 = 0.0f, rs1 = 0.0f;
        const float o0b = -nm0 * LOG2E, o1b = -nm1 * LOG2E;
        #pragma unroll
        for (int ni = 0; ni < 8; ni++) {
            unsigned e0 = h2ex2(packh2(fmaf(sacc[ni][0], LOG2E, o0b),
                                       fmaf(sacc[ni][1], LOG2E, o0b)));
            unsigned e1 = h2ex2(packh2(fmaf(sacc[ni][2], LOG2E, o1b),
                                       fmaf(sacc[ni][3], LOG2E, o1b)));
            ph[ni][0] = e0;
            ph[ni][1] = e1;
            float2 f0 = __half22float2(*(__half2*)&e0);
            float2 f1 = __half22float2(*(__half2*)&e1);
            rs0 += f0.x + f0.y;
            rs1 += f1.x + f1.y;
        }
        rs0 += __shfl_xor_sync(0xffffffffu, rs0, 1);
        rs0 += __shfl_xor_sync(0xffffffffu, rs0, 2);
        rs1 += __shfl_xor_sync(0xffffffffu, rs1, 1);
        rs1 += __shfl_xor_sync(0xffffffffu, rs1, 2);

        ls0 = ls0 * sc0 + rs0;  mr0 = nm0;
        ls1 = ls1 * sc1 + rs1;  mr1 = nm1;
        #pragma unroll
        for (int ni = 0; ni < 8; ni++) {
            oacc[ni][0] *= sc0; oacc[ni][1] *= sc0;
            oacc[ni][2] *= sc1; oacc[ni][3] *= sc1;
        }

        // O += P @ V : V B-frags via ldmatrix.trans from row-major Vs
        #pragma unroll
        for (int ks2 = 0; ks2 < 4; ks2++) {
            unsigned pa[4];
            pa[0] = ph[2 * ks2    ][0];
            pa[1] = ph[2 * ks2    ][1];
            pa[2] = ph[2 * ks2 + 1][0];
            pa[3] = ph[2 * ks2 + 1][1];
            const int kb = ks2 * 16;
            #pragma unroll
            for (int dj = 0; dj < 4; dj++) {
                unsigned b0, b1, b2, b3;
                LDSM4T(b0, b1, b2, b3,
                       vsb + ((kb + rT) * KPAD + dj * 16 + cT) * 2);
                mma_f16(oacc[2 * dj    ], pa, b0, b1);
                mma_f16(oacc[2 * dj + 1], pa, b2, b3);
            }
        }
        __syncthreads();
    }

    // Epilogue -> fp16 attention output
    const float inv0 = 1.0f / ls0, inv1 = 1.0f / ls1;
    #pragma unroll
    for (int ni = 0; ni < 8; ni++) {
        const int col = h * DH + ni * 8 + 2 * t;
        *(unsigned*)&out[((long)b * SS + rg0) * DD + col] =
            packh2(oacc[ni][0] * inv0, oacc[ni][1] * inv0);
        *(unsigned*)&out[((long)b * SS + rg1) * DD + col] =
            packh2(oacc[ni][2] * inv1, oacc[ni][3] * inv1);
    }
}

// ---------------------------------------------------------------------------
// Fused residual + LayerNorm. Optionally dual-writes an fp16 copy.
// ---------------------------------------------------------------------------
template<bool DUAL>
__global__ __launch_bounds__(256)
void ln_kernel(const float* __restrict__ resid, const float* __restrict__ y,
               const float* __restrict__ g, const float* __restrict__ beta,
               float* __restrict__ out, __half* __restrict__ out_h)
{
    __shared__ float red[16];
    __shared__ float stats[2];

    const long row = blockIdx.x;
    const int tid  = threadIdx.x;
    const long base = row * DD + tid * 4;

    float4 r  = *(const float4*)&resid[base];
    float4 yv = *(const float4*)&y[base];
    float v0 = r.x + yv.x, v1 = r.y + yv.y, v2 = r.z + yv.z, v3 = r.w + yv.w;

    float s  = v0 + v1 + v2 + v3;
    float ss = v0*v0 + v1*v1 + v2*v2 + v3*v3;
    #pragma unroll
    for (int o = 16; o > 0; o >>= 1) {
        s  += __shfl_xor_sync(0xffffffffu, s, o);
        ss += __shfl_xor_sync(0xffffffffu, ss, o);
    }
    const int warp = tid >> 5;
    if ((tid & 31) == 0) {
        red[warp * 2]     = s;
        red[warp * 2 + 1] = ss;
    }
    __syncthreads();
    if (tid == 0) {
        float ts = 0.f, tss = 0.f;
        #pragma unroll
        for (int w = 0; w < 8; w++) { ts += red[w*2]; tss += red[w*2+1]; }
        float mean = ts * (1.0f / DD);
        float var  = tss * (1.0f / DD) - mean * mean;
        stats[0] = mean;
        stats[1] = rsqrtf(var + 1e-5f);
    }
    __syncthreads();
    const float mean = stats[0];
    const float istd = stats[1];

    float4 gv = *(const float4*)&g[tid * 4];
    float4 bv = *(const float4*)&beta[tid * 4];
    float4 o;
    o.x = (v0 - mean) * istd * gv.x + bv.x;
    o.y = (v1 - mean) * istd * gv.y + bv.y;
    o.z = (v2 - mean) * istd * gv.z + bv.z;
    o.w = (v3 - mean) * istd * gv.w + bv.w;
    *(float4*)&out[base] = o;
    if (DUAL) {
        uint2 q;
        q.x = packh2(o.x, o.y);
        q.y = packh2(o.z, o.w);
        *(uint2*)&out_h[base] = q;
    }
}

// ---------------------------------------------------------------------------
// Launcher
// ---------------------------------------------------------------------------
extern "C" void kernel_launch(void* const* d_in, const int* in_sizes, int n_in,
                              void* d_out, int out_size)
{
    const float* x      = (const float*)d_in[0];
    const float* imag   = (const float*)d_in[1];
    const float* w_qkv  = (const float*)d_in[2];
    const float* b_qkv  = (const float*)d_in[3];
    const float* w_o    = (const float*)d_in[4];
    const float* b_o    = (const float*)d_in[5];
    const float* ln1_g  = (const float*)d_in[6];
    const float* ln1_b  = (const float*)d_in[7];
    const float* w1     = (const float*)d_in[8];
    const float* b1     = (const float*)d_in[9];
    const float* w2     = (const float*)d_in[10];
    const float* b2     = (const float*)d_in[11];
    const float* ln2_g  = (const float*)d_in[12];
    const float* ln2_b  = (const float*)d_in[13];
    float* out = (float*)d_out;

    __half *qkvh, *hoph, *attnh, *x1h, *f1h, *xh, *imh, *wqkvh, *woh, *w1h, *w2h;
    float *att2p, *x1p, *f2p;
    cudaGetSymbolAddress((void**)&qkvh,  g_qkvh);
    cudaGetSymbolAddress((void**)&hoph,  g_hoph);
    cudaGetSymbolAddress((void**)&attnh, g_attnh);
    cudaGetSymbolAddress((void**)&att2p, g_att2);
    cudaGetSymbolAddress((void**)&x1p,   g_x1);
    cudaGetSymbolAddress((void**)&x1h,   g_x1h);
    cudaGetSymbolAddress((void**)&f1h,   g_f1h);
    cudaGetSymbolAddress((void**)&f2p,   g_ff2);
    cudaGetSymbolAddress((void**)&xh,    g_xh);
    cudaGetSymbolAddress((void**)&imh,   g_imh);
    cudaGetSymbolAddress((void**)&wqkvh, g_wqkvh);
    cudaGetSymbolAddress((void**)&woh,   g_woh);
    cudaGetSymbolAddress((void**)&w1h,   g_w1h);
    cudaGetSymbolAddress((void**)&w2h,   g_w2h);

    cudaFuncSetAttribute((const void*)hgemm<false,float>,
                         cudaFuncAttributeMaxDynamicSharedMemorySize, GEMM_SMEM);
    cudaFuncSetAttribute((const void*)hgemm<false,__half>,
                         cudaFuncAttributeMaxDynamicSharedMemorySize, GEMM_SMEM);
    cudaFuncSetAttribute((const void*)hgemm<true,__half>,
                         cudaFuncAttributeMaxDynamicSharedMemorySize, GEMM_SMEM);

    const int MR = BB * SS;  // 8192 rows

    // 0) fp16 copies of GEMM input operands
    {
        const long nx = (long)BB * SS * DD;
        cvt_kernel<<<(int)(nx / 2048), 256>>>(x, xh, nx);
        cvt_kernel<<<(int)(nx / 2048), 256>>>(imag, imh, nx);
        const long nq = (long)3 * DD * DD;
        cvt_kernel<<<(int)(nq / 2048), 256>>>(w_qkv, wqkvh, nq);
        const long no = (long)DD * DD;
        cvt_kernel<<<(int)(no / 2048), 256>>>(w_o, woh, no);
        const long n1 = (long)4 * DD * DD;
        cvt_kernel<<<(int)(n1 / 2048), 256>>>(w1, w1h, n1);
        cvt_kernel<<<(int)(n1 / 2048), 256>>>(w2, w2h, n1);
    }

    // 1) hopping[b] = imag[b] @ imag[b]^T / sqrt(D) -> fp16 (lower tiles only)
    hgemm<false,__half><<<dim3(SS/256, SS/128, BB), 256, GEMM_SMEM>>>(
        imh, imh, nullptr, hoph, SS, SS, DD,
        (long)SS * DD, (long)SS * DD, (long)SS * SS, 0.03125f, 1);

    // 2) QKV projection -> fp16
    hgemm<false,__half><<<dim3(3*DD/256, MR/128, 1), 256, GEMM_SMEM>>>(
        xh, wqkvh, b_qkv, qkvh, MR, 3*DD, DD, 0, 0, 0, 1.0f, 0);

    // 3) FP16 tensor-core causal attention (128-row q tile, f16x2 ex2)
    attn_kernel<<<dim3(SS/128, HH, BB), 256>>>(qkvh, hoph, attnh);

    // 4) Output projection -> fp32 (feeds LN1)
    hgemm<false,float><<<dim3(DD/256, MR/128, 1), 256, GEMM_SMEM>>>(
        attnh, woh, b_o, att2p, MR, DD, DD, 0, 0, 0, 1.0f, 0);

    // 5) LN1(x + attn_out) -> exact fp32 x1 + fp16 x1h
    ln_kernel<true><<<MR, 256>>>(x, att2p, ln1_g, ln1_b, x1p, x1h);

    // 6) FFN1 + exact GELU -> fp16
    hgemm<true,__half><<<dim3(4*DD/256, MR/128, 1), 256, GEMM_SMEM>>>(
        x1h, w1h, b1, f1h, MR, 4*DD, DD, 0, 0, 0, 1.0f, 0);

    // 7) FFN2 -> fp32 (feeds LN2)
    hgemm<false,float><<<dim3(DD/256, MR/128, 1), 256, GEMM_SMEM>>>(
        f1h, w2h, b2, f2p, MR, DD, 4*DD, 0, 0, 0, 1.0f, 0);

    // 8) LN2(x1 + ffn_out) -> final output
    ln_kernel<false><<<MR, 256>>>(x1p, f2p, ln2_g, ln2_b, out, nullptr);
}

// round 13
// speedup vs baseline: 1.1000x; 1.1000x over previous
#include <cuda_runtime.h>
#include <cuda_fp16.h>
#include <cstdint>
#include <math.h>

// Problem constants
#define BB 4
#define SS 2048
#define DD 1024
#define HH 16
#define DH 64

// ---------------------------------------------------------------------------
// Scratch (device globals — no runtime allocation allowed)
// ---------------------------------------------------------------------------
__device__ __half g_qkvh [(long)BB * SS * 3 * DD];  // QKV (fp16)
__device__ __half g_hoph [(long)BB * SS * SS];      // hopping bias (fp16)
__device__ __half g_attnh[(long)BB * SS * DD];      // attention out (fp16)
__device__ float  g_att2 [(long)BB * SS * DD];      // after O-proj (fp32)
__device__ float  g_x1   [(long)BB * SS * DD];      // after LN1 (fp32, exact)
__device__ __half g_x1h  [(long)BB * SS * DD];      // after LN1 (fp16)
__device__ __half g_f1h  [(long)BB * SS * 4 * DD];  // after FFN1+GELU (fp16)
__device__ float  g_ff2  [(long)BB * SS * DD];      // after FFN2 (fp32)
// fp16 copies of inputs
__device__ __half g_xh   [(long)BB * SS * DD];
__device__ __half g_imh  [(long)BB * SS * DD];
__device__ __half g_wqkvh[(long)3 * DD * DD];
__device__ __half g_woh  [(long)DD * DD];
__device__ __half g_w1h  [(long)4 * DD * DD];
__device__ __half g_w2h  [(long)DD * 4 * DD];

// ---------------------------------------------------------------------------
// Helpers
// ---------------------------------------------------------------------------
__device__ __forceinline__ float gelu_exact(float x) {
    return 0.5f * x * (1.0f + erff(x * 0.70710678118654752f));
}
__device__ __forceinline__ unsigned packh2(float a, float b) {
    __half2 h = __floats2half2_rn(a, b);
    return *(unsigned*)&h;
}
__device__ __forceinline__ void cp_async16(unsigned saddr, const void* gmem) {
    asm volatile("cp.async.cg.shared.global [%0], [%1], 16;" :: "r"(saddr), "l"(gmem));
}
__device__ __forceinline__ void cp_commit() { asm volatile("cp.async.commit_group;"); }
template<int N> __device__ __forceinline__ void cp_wait() {
    asm volatile("cp.async.wait_group %0;" :: "n"(N));
}

// m16n8k16 fp16 mma, fp32 accumulate
__device__ __forceinline__ void mma_f16(float* c, const unsigned* a,
                                        unsigned b0, unsigned b1) {
    asm volatile(
        "mma.sync.aligned.m16n8k16.row.col.f32.f16.f16.f32 "
        "{%0,%1,%2,%3}, {%4,%5,%6,%7}, {%8,%9}, {%0,%1,%2,%3};"
        : "+f"(c[0]), "+f"(c[1]), "+f"(c[2]), "+f"(c[3])
        : "r"(a[0]), "r"(a[1]), "r"(a[2]), "r"(a[3]), "r"(b0), "r"(b1));
}

#define LDSM4(r0, r1, r2, r3, saddr) \
    asm volatile("ldmatrix.sync.aligned.m8n8.x4.shared.b16 {%0,%1,%2,%3}, [%4];" \
                 : "=r"(r0), "=r"(r1), "=r"(r2), "=r"(r3) : "r"(saddr))
#define LDSM4T(r0, r1, r2, r3, saddr) \
    asm volatile("ldmatrix.sync.aligned.m8n8.x4.trans.shared.b16 {%0,%1,%2,%3}, [%4];" \
                 : "=r"(r0), "=r"(r1), "=r"(r2), "=r"(r3) : "r"(saddr))

// Epilogue store helpers (fp32 or fp16 output)
__device__ __forceinline__ void store2(float* C, long idx, float a, float b) {
    *(float2*)&C[idx] = make_float2(a, b);
}
__device__ __forceinline__ void store2(__half* C, long idx, float a, float b) {
    *(unsigned*)&C[idx] = packh2(a, b);
}

// ---------------------------------------------------------------------------
// Single segmented fp32->fp16 convert kernel (replaces 6 launches).
// ---------------------------------------------------------------------------
struct CvtSegs {
    const float* in[6];
    __half* out[6];
    long n[6];       // element counts (each divisible by 8)
};

__global__ __launch_bounds__(256)
void cvt_all(CvtSegs segs)
{
    long base = ((long)blockIdx.x * 256 + threadIdx.x) * 8;
    #pragma unroll
    for (int s = 0; s < 6; s++) {
        if (base < segs.n[s]) {
            const float* in = segs.in[s];
            __half* out = segs.out[s];
            float4 v0 = *(const float4*)&in[base];
            float4 v1 = *(const float4*)&in[base + 4];
            uint4 q;
            q.x = packh2(v0.x, v0.y);
            q.y = packh2(v0.z, v0.w);
            q.z = packh2(v1.x, v1.y);
            q.w = packh2(v1.z, v1.w);
            *(uint4*)&out[base] = q;
            return;
        }
        base -= segs.n[s];
    }
}

// ---------------------------------------------------------------------------
// FP16 tensor-core GEMM, ldmatrix fragments, 4-stage cp.async, occupancy 2.
// C[M,N] = scale * (A[M,K] @ B[N,K]^T) + bias[N], optional exact GELU.
// 128x128x32 CTA tile, 256 threads, 8 warps (2x4), warp tile 64x32.
// Requires M%128==0, N%128==0, K%32==0, K/32>=3. causal => skip upper tiles.
// ---------------------------------------------------------------------------
#define SPADH 40                          // halves per smem row (80 B)
#define TSTG (128 * SPADH * 2)            // 10240 B per operand tile
#define STGB (2 * TSTG)                   // 20480 B per stage
#define GEMM_SMEM (4 * STGB)              // 81920 B

template<bool GELU, typename OutT>
__global__ __launch_bounds__(256, 2)
void hgemm(const __half* __restrict__ A, const __half* __restrict__ B,
           const float* __restrict__ bias, OutT* __restrict__ C,
           int M, int N, int K, long sA, long sB, long sC,
           float scale, int causal)
{
    extern __shared__ __half smem[];
    const unsigned sb = (unsigned)__cvta_generic_to_shared(smem);

    const int tid  = threadIdx.x;
    const int warp = tid >> 5;
    const int lane = tid & 31;
    const int g    = lane >> 2;
    const int t    = lane & 3;
    const int m0   = blockIdx.y * 128;
    const int n0   = blockIdx.x * 128;

    if (causal && n0 > m0 + 127) return;

    const int z = blockIdx.z;
    A += (long)z * sA;
    B += (long)z * sB;
    C += (long)z * sC;

    const int wm = (warp & 1) * 64;    // warp m offset (0,64)
    const int wn = (warp >> 1) * 32;   // warp n offset (0,32,64,96)

    float acc[4][4][4];
    #pragma unroll
    for (int mi = 0; mi < 4; mi++)
        #pragma unroll
        for (int ni = 0; ni < 4; ni++)
            #pragma unroll
            for (int c = 0; c < 4; c++)
                acc[mi][ni][c] = 0.0f;

    const int raA = wm + (lane & 7) + (((lane >> 3) & 1) << 3);
    const int caA = ((lane >> 4) << 3);
    const int raB = wn + (lane & 7) + ((lane >> 4) << 3);
    const int caB = (((lane >> 3) & 1) << 3);

    const int niter = K >> 5;

    // cp.async staging: each operand tile 128x32 halves = 512 16B chunks;
    // 1024 total / 256 threads = 4 per thread (2 A + 2 B).
    const int lr = tid >> 2;          // rows 0..63 (then +64)
    const int lc = (tid & 3) * 8;     // half-cols 0,8,16,24

    #define STAGE(s, k0)                                                        \
        {                                                                       \
            unsigned ab = sb + (s) * STGB;                                      \
            unsigned bb = ab + TSTG;                                            \
            _Pragma("unroll")                                                   \
            for (int l = 0; l < 2; l++) {                                       \
                int row = lr + l * 64;                                          \
                cp_async16(ab + (row * SPADH + lc) * 2,                         \
                           &A[(long)(m0 + row) * K + (k0) + lc]);               \
                cp_async16(bb + (row * SPADH + lc) * 2,                         \
                           &B[(long)(n0 + row) * K + (k0) + lc]);               \
            }                                                                   \
        }

    STAGE(0, 0);  cp_commit();
    STAGE(1, 32); cp_commit();
    STAGE(2, 64); cp_commit();

    for (int i = 0; i < niter; i++) {
        cp_wait<2>();
        __syncthreads();

        const unsigned As = sb + (i & 3) * STGB;
        const unsigned Bs = As + TSTG;

        #pragma unroll
        for (int ks = 0; ks < 2; ks++) {
            const int kb = ks * 16;
            unsigned a[4][4], b[2][4];
            #pragma unroll
            for (int mi = 0; mi < 4; mi++)
                LDSM4(a[mi][0], a[mi][1], a[mi][2], a[mi][3],
                      As + ((raA + mi * 16) * SPADH + kb + caA) * 2);
            #pragma unroll
            for (int nj = 0; nj < 2; nj++)
                LDSM4(b[nj][0], b[nj][1], b[nj][2], b[nj][3],
                      Bs + ((raB + nj * 16) * SPADH + kb + caB) * 2);
            #pragma unroll
            for (int mi = 0; mi < 4; mi++)
                #pragma unroll
                for (int nj = 0; nj < 2; nj++) {
                    mma_f16(acc[mi][2 * nj    ], a[mi], b[nj][0], b[nj][1]);
                    mma_f16(acc[mi][2 * nj + 1], a[mi], b[nj][2], b[nj][3]);
                }
        }

        if (i + 3 < niter) STAGE((i + 3) & 3, (i + 3) * 32);
        cp_commit();
    }
    #undef STAGE

    // Epilogue
    #pragma unroll
    for (int mi = 0; mi < 4; mi++) {
        const int row0 = m0 + wm + mi * 16 + g;
        #pragma unroll
        for (int ni = 0; ni < 4; ni++) {
            const int col = n0 + wn + ni * 8 + 2 * t;
            float bx = 0.0f, by = 0.0f;
            if (bias) { bx = bias[col]; by = bias[col + 1]; }
            float o0 = acc[mi][ni][0] * scale + bx;
            float o1 = acc[mi][ni][1] * scale + by;
            float o2 = acc[mi][ni][2] * scale + bx;
            float o3 = acc[mi][ni][3] * scale + by;
            if (GELU) {
                o0 = gelu_exact(o0); o1 = gelu_exact(o1);
                o2 = gelu_exact(o2); o3 = gelu_exact(o3);
            }
            store2(C, (long)row0 * N + col, o0, o1);
            store2(C, (long)(row0 + 8) * N + col, o2, o3);
        }
    }
}

// ---------------------------------------------------------------------------
// FP16 tensor-core flash attention, 128-row q tile, fp16 hopping bias.
// (R11 configuration: __expf softmax — measured best.)
// Grid: (S/128, H, B). Block: 256 threads (8 warps).
// ---------------------------------------------------------------------------
#define KPAD 72
__global__ __launch_bounds__(256, 2)
void attn_kernel(const __half* __restrict__ qkv, const __half* __restrict__ hop,
                 __half* __restrict__ out)
{
    __shared__ __half Ks[64][KPAD];   // [key][d]
    __shared__ __half Vs[64][KPAD];   // [key][d]

    const int tid  = threadIdx.x;
    const int lane = tid & 31;
    const int warp = tid >> 5;
    const int g    = lane >> 2;
    const int t    = lane & 3;
    const int qb = blockIdx.x, h = blockIdx.y, b = blockIdx.z;
    const int q0 = qb * 128;
    const long rowbase = (long)b * SS * (3 * DD);
    const long hb      = (long)b * SS * SS;
    const int rg0 = q0 + warp * 16 + g;   // first owned row (global)
    const int rg1 = rg0 + 8;

    const unsigned ksb = (unsigned)__cvta_generic_to_shared(&Ks[0][0]);
    const unsigned vsb = (unsigned)__cvta_generic_to_shared(&Vs[0][0]);
    const int rB = (lane & 7) + ((lane >> 4) << 3);          // non-trans rows
    const int cB = (((lane >> 3) & 1) << 3);                 // non-trans col half
    const int rT = (lane & 7) + (((lane >> 3) & 1) << 3);    // trans rows (keys)
    const int cT = ((lane >> 4) << 3);                       // trans col half (d)

    // ---- Q A-fragments straight from gmem ----
    unsigned qa[4][4];
    {
        const long q0r = rowbase + (long)rg0 * (3 * DD) + h * DH;
        const long q1r = rowbase + (long)rg1 * (3 * DD) + h * DH;
        #pragma unroll
        for (int ks = 0; ks < 4; ks++) {
            const int kb = ks * 16 + 2 * t;
            qa[ks][0] = *(const unsigned*)&qkv[q0r + kb];
            qa[ks][1] = *(const unsigned*)&qkv[q1r + kb];
            qa[ks][2] = *(const unsigned*)&qkv[q0r + kb + 8];
            qa[ks][3] = *(const unsigned*)&qkv[q1r + kb + 8];
        }
    }

    float mr0 = -1e30f, mr1 = -1e30f, ls0 = 0.0f, ls1 = 0.0f;
    float oacc[8][4];
    #pragma unroll
    for (int ni = 0; ni < 8; ni++)
        #pragma unroll
        for (int c = 0; c < 4; c++) oacc[ni][c] = 0.0f;

    const int ktmax = 2 * qb + 2;
    for (int kt = 0; kt < ktmax; kt++) {
        const int k0 = kt * 64;

        // Stage K and V (row-major, vectorized, conflict-free)
        #pragma unroll
        for (int l = 0; l < 2; l++) {
            int idx = tid + l * 256, r = idx >> 3, c = (idx & 7) * 8;
            long base = rowbase + (long)(k0 + r) * (3 * DD) + h * DH + c;
            *(uint4*)&Ks[r][c] = *(const uint4*)&qkv[base + DD];
            *(uint4*)&Vs[r][c] = *(const uint4*)&qkv[base + 2 * DD];
        }
        __syncthreads();

        // Hopping bias prefetch (fp16 -> fp32)
        float2 hp0[8], hp1[8];
        #pragma unroll
        for (int ni = 0; ni < 8; ni++) {
            __half2 u0 = *(const __half2*)&hop[hb + (long)rg0 * SS + k0 + ni * 8 + 2 * t];
            __half2 u1 = *(const __half2*)&hop[hb + (long)rg1 * SS + k0 + ni * 8 + 2 * t];
            hp0[ni] = __half22float2(u0);
            hp1[ni] = __half22float2(u1);
        }

        // S = Q @ K^T
        float sacc[8][4];
        #pragma unroll
        for (int ni = 0; ni < 8; ni++)
            #pragma unroll
            for (int c = 0; c < 4; c++) sacc[ni][c] = 0.0f;
        #pragma unroll
        for (int ks = 0; ks < 4; ks++) {
            const int kb = ks * 16;
            #pragma unroll
            for (int nj = 0; nj < 4; nj++) {
                unsigned b0, b1, b2, b3;
                LDSM4(b0, b1, b2, b3,
                      ksb + ((nj * 16 + rB) * KPAD + kb + cB) * 2);
                mma_f16(sacc[2 * nj    ], qa[ks], b0, b1);
                mma_f16(sacc[2 * nj + 1], qa[ks], b2, b3);
            }
        }

        // scale + bias (+ causal mask on diagonal-straddling tiles)
        #pragma unroll
        for (int ni = 0; ni < 8; ni++) {
            sacc[ni][0] = sacc[ni][0] * 0.125f + hp0[ni].x;
            sacc[ni][1] = sacc[ni][1] * 0.125f + hp0[ni].y;
            sacc[ni][2] = sacc[ni][2] * 0.125f + hp1[ni].x;
            sacc[ni][3] = sacc[ni][3] * 0.125f + hp1[ni].y;
        }
        if (kt >= 2 * qb) {   // global row/col compare
            #pragma unroll
            for (int ni = 0; ni < 8; ni++) {
                int c0 = k0 + ni * 8 + 2 * t, c1 = c0 + 1;
                if (c0 > rg0) sacc[ni][0] = -1e30f;
                if (c1 > rg0) sacc[ni][1] = -1e30f;
                if (c0 > rg1) sacc[ni][2] = -1e30f;
                if (c1 > rg1) sacc[ni][3] = -1e30f;
            }
        }

        // Warp-local online softmax
        float rm0 = -1e30f, rm1 = -1e30f;
        #pragma unroll
        for (int ni = 0; ni < 8; ni++) {
            rm0 = fmaxf(rm0, fmaxf(sacc[ni][0], sacc[ni][1]));
            rm1 = fmaxf(rm1, fmaxf(sacc[ni][2], sacc[ni][3]));
        }
        rm0 = fmaxf(rm0, __shfl_xor_sync(0xffffffffu, rm0, 1));
        rm0 = fmaxf(rm0, __shfl_xor_sync(0xffffffffu, rm0, 2));
        rm1 = fmaxf(rm1, __shfl_xor_sync(0xffffffffu, rm1, 1));
        rm1 = fmaxf(rm1, __shfl_xor_sync(0xffffffffu, rm1, 2));

        const float nm0 = fmaxf(mr0, rm0), nm1 = fmaxf(mr1, rm1);
        const float sc0 = __expf(mr0 - nm0), sc1 = __expf(mr1 - nm1);
        float rs0 = 0.0f, rs1 = 0.0f;
        #pragma unroll
        for (int ni = 0; ni < 8; ni++) {
            sacc[ni][0] = __expf(sacc[ni][0] - nm0);
            sacc[ni][1] = __expf(sacc[ni][1] - nm0);
            sacc[ni][2] = __expf(sacc[ni][2] - nm1);
            sacc[ni][3] = __expf(sacc[ni][3] - nm1);
            rs0 += sacc[ni][0] + sacc[ni][1];
            rs1 += sacc[ni][2] + sacc[ni][3];
        }
        rs0 += __shfl_xor_sync(0xffffffffu, rs0, 1);
        rs0 += __shfl_xor_sync(0xffffffffu, rs0, 2);
        rs1 += __shfl_xor_sync(0xffffffffu, rs1, 1);
        rs1 += __shfl_xor_sync(0xffffffffu, rs1, 2);

        ls0 = ls0 * sc0 + rs0;  mr0 = nm0;
        ls1 = ls1 * sc1 + rs1;  mr1 = nm1;
        #pragma unroll
        for (int ni = 0; ni < 8; ni++) {
            oacc[ni][0] *= sc0; oacc[ni][1] *= sc0;
            oacc[ni][2] *= sc1; oacc[ni][3] *= sc1;
        }

        // O += P @ V : V B-frags via ldmatrix.trans from row-major Vs
        #pragma unroll
        for (int ks2 = 0; ks2 < 4; ks2++) {
            unsigned pa[4];
            pa[0] = packh2(sacc[2 * ks2    ][0], sacc[2 * ks2    ][1]);
            pa[1] = packh2(sacc[2 * ks2    ][2], sacc[2 * ks2    ][3]);
            pa[2] = packh2(sacc[2 * ks2 + 1][0], sacc[2 * ks2 + 1][1]);
            pa[3] = packh2(sacc[2 * ks2 + 1][2], sacc[2 * ks2 + 1][3]);
            const int kb = ks2 * 16;
            #pragma unroll
            for (int dj = 0; dj < 4; dj++) {
                unsigned b0, b1, b2, b3;
                LDSM4T(b0, b1, b2, b3,
                       vsb + ((kb + rT) * KPAD + dj * 16 + cT) * 2);
                mma_f16(oacc[2 * dj    ], pa, b0, b1);
                mma_f16(oacc[2 * dj + 1], pa, b2, b3);
            }
        }
        __syncthreads();
    }

    // Epilogue -> fp16 attention output
    const float inv0 = 1.0f / ls0, inv1 = 1.0f / ls1;
    #pragma unroll
    for (int ni = 0; ni < 8; ni++) {
        const int col = h * DH + ni * 8 + 2 * t;
        *(unsigned*)&out[((long)b * SS + rg0) * DD + col] =
            packh2(oacc[ni][0] * inv0, oacc[ni][1] * inv0);
        *(unsigned*)&out[((long)b * SS + rg1) * DD + col] =
            packh2(oacc[ni][2] * inv1, oacc[ni][3] * inv1);
    }
}

// ---------------------------------------------------------------------------
// Fused residual + LayerNorm. Optionally dual-writes an fp16 copy.
// ---------------------------------------------------------------------------
template<bool DUAL>
__global__ __launch_bounds__(256)
void ln_kernel(const float* __restrict__ resid, const float* __restrict__ y,
               const float* __restrict__ g, const float* __restrict__ beta,
               float* __restrict__ out, __half* __restrict__ out_h)
{
    __shared__ float red[16];
    __shared__ float stats[2];

    const long row = blockIdx.x;
    const int tid  = threadIdx.x;
    const long base = row * DD + tid * 4;

    float4 r  = *(const float4*)&resid[base];
    float4 yv = *(const float4*)&y[base];
    float v0 = r.x + yv.x, v1 = r.y + yv.y, v2 = r.z + yv.z, v3 = r.w + yv.w;

    float s  = v0 + v1 + v2 + v3;
    float ss = v0*v0 + v1*v1 + v2*v2 + v3*v3;
    #pragma unroll
    for (int o = 16; o > 0; o >>= 1) {
        s  += __shfl_xor_sync(0xffffffffu, s, o);
        ss += __shfl_xor_sync(0xffffffffu, ss, o);
    }
    const int warp = tid >> 5;
    if ((tid & 31) == 0) {
        red[warp * 2]     = s;
        red[warp * 2 + 1] = ss;
    }
    __syncthreads();
    if (tid == 0) {
        float ts = 0.f, tss = 0.f;
        #pragma unroll
        for (int w = 0; w < 8; w++) { ts += red[w*2]; tss += red[w*2+1]; }
        float mean = ts * (1.0f / DD);
        float var  = tss * (1.0f / DD) - mean * mean;
        stats[0] = mean;
        stats[1] = rsqrtf(var + 1e-5f);
    }
    __syncthreads();
    const float mean = stats[0];
    const float istd = stats[1];

    float4 gv = *(const float4*)&g[tid * 4];
    float4 bv = *(const float4*)&beta[tid * 4];
    float4 o;
    o.x = (v0 - mean) * istd * gv.x + bv.x;
    o.y = (v1 - mean) * istd * gv.y + bv.y;
    o.z = (v2 - mean) * istd * gv.z + bv.z;
    o.w = (v3 - mean) * istd * gv.w + bv.w;
    *(float4*)&out[base] = o;
    if (DUAL) {
        uint2 q;
        q.x = packh2(o.x, o.y);
        q.y = packh2(o.z, o.w);
        *(uint2*)&out_h[base] = q;
    }
}

// ---------------------------------------------------------------------------
// Launcher
// ---------------------------------------------------------------------------
extern "C" void kernel_launch(void* const* d_in, const int* in_sizes, int n_in,
                              void* d_out, int out_size)
{
    const float* x      = (const float*)d_in[0];
    const float* imag   = (const float*)d_in[1];
    const float* w_qkv  = (const float*)d_in[2];
    const float* b_qkv  = (const float*)d_in[3];
    const float* w_o    = (const float*)d_in[4];
    const float* b_o    = (const float*)d_in[5];
    const float* ln1_g  = (const float*)d_in[6];
    const float* ln1_b  = (const float*)d_in[7];
    const float* w1     = (const float*)d_in[8];
    const float* b1     = (const float*)d_in[9];
    const float* w2     = (const float*)d_in[10];
    const float* b2     = (const float*)d_in[11];
    const float* ln2_g  = (const float*)d_in[12];
    const float* ln2_b  = (const float*)d_in[13];
    float* out = (float*)d_out;

    __half *qkvh, *hoph, *attnh, *x1h, *f1h, *xh, *imh, *wqkvh, *woh, *w1h, *w2h;
    float *att2p, *x1p, *f2p;
    cudaGetSymbolAddress((void**)&qkvh,  g_qkvh);
    cudaGetSymbolAddress((void**)&hoph,  g_hoph);
    cudaGetSymbolAddress((void**)&attnh, g_attnh);
    cudaGetSymbolAddress((void**)&att2p, g_att2);
    cudaGetSymbolAddress((void**)&x1p,   g_x1);
    cudaGetSymbolAddress((void**)&x1h,   g_x1h);
    cudaGetSymbolAddress((void**)&f1h,   g_f1h);
    cudaGetSymbolAddress((void**)&f2p,   g_ff2);
    cudaGetSymbolAddress((void**)&xh,    g_xh);
    cudaGetSymbolAddress((void**)&imh,   g_imh);
    cudaGetSymbolAddress((void**)&wqkvh, g_wqkvh);
    cudaGetSymbolAddress((void**)&woh,   g_woh);
    cudaGetSymbolAddress((void**)&w1h,   g_w1h);
    cudaGetSymbolAddress((void**)&w2h,   g_w2h);

    cudaFuncSetAttribute((const void*)hgemm<false,float>,
                         cudaFuncAttributeMaxDynamicSharedMemorySize, GEMM_SMEM);
    cudaFuncSetAttribute((const void*)hgemm<false,__half>,
                         cudaFuncAttributeMaxDynamicSharedMemorySize, GEMM_SMEM);
    cudaFuncSetAttribute((const void*)hgemm<true,__half>,
                         cudaFuncAttributeMaxDynamicSharedMemorySize, GEMM_SMEM);

    const int MR = BB * SS;  // 8192 rows

    // 0) fp16 copies of all GEMM input operands in ONE kernel
    {
        CvtSegs segs;
        const long nx = (long)BB * SS * DD;
        segs.in[0] = x;      segs.out[0] = xh;    segs.n[0] = nx;
        segs.in[1] = imag;   segs.out[1] = imh;   segs.n[1] = nx;
        segs.in[2] = w_qkv;  segs.out[2] = wqkvh; segs.n[2] = (long)3 * DD * DD;
        segs.in[3] = w_o;    segs.out[3] = woh;   segs.n[3] = (long)DD * DD;
        segs.in[4] = w1;     segs.out[4] = w1h;   segs.n[4] = (long)4 * DD * DD;
        segs.in[5] = w2;     segs.out[5] = w2h;   segs.n[5] = (long)DD * 4 * DD;
        long total = segs.n[0] + segs.n[1] + segs.n[2] + segs.n[3] + segs.n[4] + segs.n[5];
        cvt_all<<<(int)(total / 2048), 256>>>(segs);
    }

    // 1) hopping[b] = imag[b] @ imag[b]^T / sqrt(D) -> fp16 (lower tiles only)
    hgemm<false,__half><<<dim3(SS/128, SS/128, BB), 256, GEMM_SMEM>>>(
        imh, imh, nullptr, hoph, SS, SS, DD,
        (long)SS * DD, (long)SS * DD, (long)SS * SS, 0.03125f, 1);

    // 2) QKV projection -> fp16
    hgemm<false,__half><<<dim3(3*DD/128, MR/128, 1), 256, GEMM_SMEM>>>(
        xh, wqkvh, b_qkv, qkvh, MR, 3*DD, DD, 0, 0, 0, 1.0f, 0);

    // 3) FP16 tensor-core causal attention (128-row q tile)
    attn_kernel<<<dim3(SS/128, HH, BB), 256>>>(qkvh, hoph, attnh);

    // 4) Output projection -> fp32 (feeds LN1)
    hgemm<false,float><<<dim3(DD/128, MR/128, 1), 256, GEMM_SMEM>>>(
        attnh, woh, b_o, att2p, MR, DD, DD, 0, 0, 0, 1.0f, 0);

    // 5) LN1(x + attn_out) -> exact fp32 x1 + fp16 x1h
    ln_kernel<true><<<MR, 256>>>(x, att2p, ln1_g, ln1_b, x1p, x1h);

    // 6) FFN1 + exact GELU -> fp16
    hgemm<true,__half><<<dim3(4*DD/128, MR/128, 1), 256, GEMM_SMEM>>>(
        x1h, w1h, b1, f1h, MR, 4*DD, DD, 0, 0, 0, 1.0f, 0);

    // 7) FFN2 -> fp32 (feeds LN2)
    hgemm<false,float><<<dim3(DD/128, MR/128, 1), 256, GEMM_SMEM>>>(
        f1h, w2h, b2, f2p, MR, DD, 4*DD, 0, 0, 0, 1.0f, 0);

    // 8) LN2(x1 + ffn_out) -> final output
    ln_kernel<false><<<MR, 256>>>(x1p, f2p, ln2_g, ln2_b, out, nullptr);
}